// round 6
// baseline (speedup 1.0000x reference)
#include <cuda_runtime.h>

// Problem constants
constexpr int BATCH = 8192;
constexpr int HDIM  = 512;      // H
constexpr int KKNOT = 16;       // K
constexpr int NBIG  = HDIM * KKNOT;  // 8192 columns of GEMM2
constexpr int NTILES_N = NBIG / 128; // 64

// Scratch (device globals: no allocation allowed)
__device__ float g_h[BATCH * HDIM];          // 16 MB: tanh((v_passive-0.5)@W1+b1)
__device__ float g_partial[BATCH * NTILES_N]; // 2 MB: per-(row, n-tile) sum of (logZ - u_k)

__device__ __forceinline__ float fast_tanh(float x) {
    float y;
    asm("tanh.approx.f32 %0, %1;" : "=f"(y) : "f"(x));
    return y;
}

// e^u for u in [-1,1], degree-8 Taylor (rel err ~7e-6), pure FMA pipe
__device__ __forceinline__ float exp_poly(float u) {
    float r = 2.48015873e-05f;
    r = fmaf(r, u, 1.98412698e-04f);
    r = fmaf(r, u, 1.38888889e-03f);
    r = fmaf(r, u, 8.33333333e-03f);
    r = fmaf(r, u, 4.16666667e-02f);
    r = fmaf(r, u, 1.66666667e-01f);
    r = fmaf(r, u, 0.5f);
    r = fmaf(r, u, 1.0f);
    r = fmaf(r, u, 1.0f);
    return r;
}

// ---------------------------------------------------------------------------
// Kernel: copy v_passive -> out[:, :512]
// ---------------------------------------------------------------------------
__global__ void k_copy_passive(const float* __restrict__ v_in, float* __restrict__ out) {
    int i = blockIdx.x * 256 + threadIdx.x;      // over BATCH * 128 float4
    int r = i >> 7;
    int c = i & 127;
    const float4* vi = (const float4*)v_in;
    float4* o = (float4*)out;
    o[r * 256 + c] = vi[r * 256 + c];            // row stride 1024 floats = 256 float4
}

// ---------------------------------------------------------------------------
// GEMM1: g_h = tanh((v_passive - 0.5) @ W1 + b1)
// 128x128 tile, BK=8, 256 threads, 8x8 per thread
// ---------------------------------------------------------------------------
__global__ __launch_bounds__(256) void k_gemm1(const float* __restrict__ v_in,
                                               const float* __restrict__ W1,
                                               const float* __restrict__ b1) {
    __shared__ float As[8][128];
    __shared__ float Bs[8][128];
    const int t  = threadIdx.x;
    const int m0 = blockIdx.y * 128;
    const int n0 = blockIdx.x * 128;
    const int ar = t >> 1, ac = (t & 1) * 4;     // A: 128 rows x 8 k
    const int br = t >> 5, bc = (t & 31) * 4;    // B: 8 k x 128 n
    const int tx = t & 15, ty = t >> 4;

    float acc[8][8];
#pragma unroll
    for (int i = 0; i < 8; i++)
#pragma unroll
        for (int j = 0; j < 8; j++) acc[i][j] = 0.f;

    const float* Aptr = v_in + (m0 + ar) * 1024 + ac;       // v_passive part
    const float* Bptr = W1 + br * HDIM + n0 + bc;

    for (int k0 = 0; k0 < HDIM; k0 += 8) {
        float4 a4 = *(const float4*)(Aptr + k0);
        float4 b4 = *(const float4*)(Bptr + k0 * HDIM);
        As[ac + 0][ar] = a4.x - 0.5f;
        As[ac + 1][ar] = a4.y - 0.5f;
        As[ac + 2][ar] = a4.z - 0.5f;
        As[ac + 3][ar] = a4.w - 0.5f;
        *(float4*)&Bs[br][bc] = b4;
        __syncthreads();
#pragma unroll
        for (int kk = 0; kk < 8; kk++) {
            float4 a0 = *(const float4*)&As[kk][ty * 4];
            float4 a1 = *(const float4*)&As[kk][64 + ty * 4];
            float4 bb0 = *(const float4*)&Bs[kk][tx * 4];
            float4 bb1 = *(const float4*)&Bs[kk][64 + tx * 4];
            float ra[8] = {a0.x, a0.y, a0.z, a0.w, a1.x, a1.y, a1.z, a1.w};
            float rb[8] = {bb0.x, bb0.y, bb0.z, bb0.w, bb1.x, bb1.y, bb1.z, bb1.w};
#pragma unroll
            for (int i = 0; i < 8; i++)
#pragma unroll
                for (int j = 0; j < 8; j++) acc[i][j] = fmaf(ra[i], rb[j], acc[i][j]);
        }
        __syncthreads();
    }

#pragma unroll
    for (int i = 0; i < 8; i++) {
        int r = m0 + ((i < 4) ? (ty * 4 + i) : (64 + ty * 4 + i - 4));
#pragma unroll
        for (int j = 0; j < 8; j++) {
            int c = n0 + ((j < 4) ? (tx * 4 + j) : (64 + tx * 4 + j - 4));
            g_h[r * HDIM + c] = fast_tanh(acc[i][j] + b1[c]);
        }
    }
}

// ---------------------------------------------------------------------------
// GEMM2 + fused spline epilogue.
// net_tile = tanh(g_h @ W2 + b2) staged in SMEM (u values), then per 16-col
// group: softmax, spline interpolation, -log p_k partial sum.
// ---------------------------------------------------------------------------
__global__ __launch_bounds__(256) void k_gemm2(const float* __restrict__ W2,
                                               const float* __restrict__ b2,
                                               const float* __restrict__ v_in,
                                               float* __restrict__ out) {
    __shared__ float As[8][128];
    __shared__ float Bs[8][128];
    __shared__ float U[64 * 129];      // 64 rows of tanh values (two phases)
    __shared__ float partial2[256];

    const int t  = threadIdx.x;
    const int m0 = blockIdx.y * 128;
    const int n0 = blockIdx.x * 128;
    const int ar = t >> 1, ac = (t & 1) * 4;
    const int br = t >> 5, bc = (t & 31) * 4;
    const int tx = t & 15, ty = t >> 4;

    float acc[8][8];
#pragma unroll
    for (int i = 0; i < 8; i++)
#pragma unroll
        for (int j = 0; j < 8; j++) acc[i][j] = 0.f;

    const float* Aptr = g_h + (m0 + ar) * HDIM + ac;
    const float* Bptr = W2 + br * NBIG + n0 + bc;

    for (int k0 = 0; k0 < HDIM; k0 += 8) {
        float4 a4 = *(const float4*)(Aptr + k0);
        float4 b4 = *(const float4*)(Bptr + k0 * NBIG);
        As[ac + 0][ar] = a4.x;
        As[ac + 1][ar] = a4.y;
        As[ac + 2][ar] = a4.z;
        As[ac + 3][ar] = a4.w;
        *(float4*)&Bs[br][bc] = b4;
        __syncthreads();
#pragma unroll
        for (int kk = 0; kk < 8; kk++) {
            float4 a0 = *(const float4*)&As[kk][ty * 4];
            float4 a1 = *(const float4*)&As[kk][64 + ty * 4];
            float4 bb0 = *(const float4*)&Bs[kk][tx * 4];
            float4 bb1 = *(const float4*)&Bs[kk][64 + tx * 4];
            float ra[8] = {a0.x, a0.y, a0.z, a0.w, a1.x, a1.y, a1.z, a1.w};
            float rb[8] = {bb0.x, bb0.y, bb0.z, bb0.w, bb1.x, bb1.y, bb1.z, bb1.w};
#pragma unroll
            for (int i = 0; i < 8; i++)
#pragma unroll
                for (int j = 0; j < 8; j++) acc[i][j] = fmaf(ra[i], rb[j], acc[i][j]);
        }
        __syncthreads();
    }

    // ---- Epilogue in two 64-row phases (keeps static SMEM < 48 KB) ----
#pragma unroll
    for (int p = 0; p < 2; p++) {
        __syncthreads();   // protect previous U reads / mainloop
        // stage u = tanh(acc + b2) for local rows [0,64): acc rows p*4..p*4+3
#pragma unroll
        for (int i = 0; i < 4; i++) {
            int ii = p * 4 + i;
            int rloc = ty * 4 + i;
#pragma unroll
            for (int j = 0; j < 8; j++) {
                int cloc = (j < 4) ? (tx * 4 + j) : (64 + tx * 4 + (j - 4));
                U[rloc * 129 + cloc] = fast_tanh(acc[ii][j] + b2[n0 + cloc]);
            }
        }
        __syncthreads();

        // 64 rows x 8 groups; thread t -> row (t&63), group pair ((t>>6)*2 ..)
        const int rloc = t & 63;
        const int q    = t >> 6;
        const int grow = m0 + p * 64 + rloc;
        float nlp = 0.f;
#pragma unroll
        for (int gg = 0; gg < 2; gg++) {
            int g    = q * 2 + gg;
            int hidx = (n0 >> 4) + g;                     // global h index
            float a  = v_in[grow * 1024 + 512 + hidx];    // v_active
            float tk = a * 16.0f;                          // exact
            int k = (int)ceilf(tk) - 1;
            k = k < 0 ? 0 : (k > 15 ? 15 : k);
            const float* up = &U[rloc * 129 + g * 16];
            float Z = 0.f, prefix = 0.f, sk = 0.f, uk = 0.f;
#pragma unroll
            for (int j = 0; j < 16; j++) {
                float u = up[j];
                float sj = exp_poly(u);
                Z += sj;
                prefix += (j < k) ? sj : 0.f;
                if (j == k) { sk = sj; uk = u; }
            }
            float alpha = tk - (float)k;
            out[grow * 1024 + 512 + hidx] = __fdividef(fmaf(alpha, sk, prefix), Z);
            nlp += __logf(Z) - uk;     // = -log p_k
        }
        partial2[t] = nlp;
        __syncthreads();
        if (t < 64) {
            float s = partial2[t] + partial2[64 + t] + partial2[128 + t] + partial2[192 + t];
            g_partial[(m0 + p * 64 + t) * NTILES_N + blockIdx.x] = s;
        }
    }
}

// ---------------------------------------------------------------------------
// Reduce per-row partials -> log_density_out
// ---------------------------------------------------------------------------
__global__ void k_reduce(const float* __restrict__ log_density,
                         float* __restrict__ out, int ld_offset) {
    int r = blockIdx.x * 256 + threadIdx.x;
    if (r >= BATCH) return;
    float s = log_density[r];
    const float4* p4 = (const float4*)&g_partial[r * NTILES_N];
#pragma unroll
    for (int i = 0; i < NTILES_N / 4; i++) {
        float4 v = p4[i];
        s += v.x + v.y + v.z + v.w;
    }
    out[ld_offset + r] = s;
}

// ---------------------------------------------------------------------------
extern "C" void kernel_launch(void* const* d_in, const int* in_sizes, int n_in,
                              void* d_out, int out_size) {
    const float* v_in        = (const float*)d_in[0];
    const float* log_density = (const float*)d_in[1];
    const float* W1          = (const float*)d_in[2];
    const float* b1          = (const float*)d_in[3];
    const float* W2          = (const float*)d_in[4];
    const float* b2          = (const float*)d_in[5];
    float* out = (float*)d_out;

    int ld_offset = out_size - BATCH;   // log_density_out follows v_out

    k_copy_passive<<<BATCH * 128 / 256, 256>>>(v_in, out);
    k_gemm1<<<dim3(HDIM / 128, BATCH / 128), 256>>>(v_in, W1, b1);
    k_gemm2<<<dim3(NBIG / 128, BATCH / 128), 256>>>(W2, b2, v_in, out);
    k_reduce<<<BATCH / 256, 256>>>(log_density, out, ld_offset);
}

// round 7
// speedup vs baseline: 3.7105x; 3.7105x over previous
#include <cuda_runtime.h>
#include <cstdint>

constexpr int BATCH = 8192;
constexpr int HDIM  = 512;
constexpr int NBIG  = 8192;       // H*K columns of GEMM2
constexpr int NTILES_N = 64;      // 8192 / 128

__device__ float g_h[BATCH * HDIM];           // tanh((v_passive-0.5)@W1+b1)
__device__ float g_partial[BATCH * NTILES_N]; // per-(row, n-tile) sum of (logZ - u_k)

__device__ __forceinline__ float fast_tanh(float x) {
    float y;
    asm("tanh.approx.f32 %0, %1;" : "=f"(y) : "f"(x));
    return y;
}

// e^u for u in [-1,1], degree-8 Taylor (rel err ~7e-6), pure FMA pipe
__device__ __forceinline__ float exp_poly(float u) {
    float r = 2.48015873e-05f;
    r = fmaf(r, u, 1.98412698e-04f);
    r = fmaf(r, u, 1.38888889e-03f);
    r = fmaf(r, u, 8.33333333e-03f);
    r = fmaf(r, u, 4.16666667e-02f);
    r = fmaf(r, u, 1.66666667e-01f);
    r = fmaf(r, u, 0.5f);
    r = fmaf(r, u, 1.0f);
    r = fmaf(r, u, 1.0f);
    return r;
}

__device__ __forceinline__ uint32_t f2tf32(float f) {
    uint32_t u;
    asm("cvt.rna.tf32.f32 %0, %1;" : "=r"(u) : "f"(f));
    return u;
}

__device__ __forceinline__ void mma_tf32(float* c, const uint32_t* a, const uint32_t* b) {
    asm volatile(
        "mma.sync.aligned.m16n8k8.row.col.f32.tf32.tf32.f32 "
        "{%0,%1,%2,%3}, {%4,%5,%6,%7}, {%8,%9}, {%0,%1,%2,%3};\n"
        : "+f"(c[0]), "+f"(c[1]), "+f"(c[2]), "+f"(c[3])
        : "r"(a[0]), "r"(a[1]), "r"(a[2]), "r"(a[3]), "r"(b[0]), "r"(b[1]));
}

#define CPA16(dst, src) \
    asm volatile("cp.async.cg.shared.global [%0], [%1], 16;\n" :: "r"(dst), "l"(src))

// smem layout (floats): A bufs [2][128][20], B bufs [2][16][136]
constexpr int A_STRIDE = 20;          // pad: fragment LDS conflict-free
constexpr int B_STRIDE = 136;         // pad: fragment LDS conflict-free
constexpr int A_BUF = 128 * A_STRIDE; // 2560
constexpr int B_BUF = 16 * B_STRIDE;  // 2176
constexpr int B_OFF = 2 * A_BUF;      // 5120
constexpr int SMEM_FLOATS = 2 * A_BUF + 2 * B_BUF;  // 9472 (37888 B)

// ---------------------------------------------------------------------------
// Unified tf32 tensor-core GEMM (128x128 tile, BK=16, 4 warps @ 64x64 each).
// MODE 0: C = tanh((A - 0.5) @ B + bias) -> g_h        (A = v_in, LDA=1024)
// MODE 1: fused spline epilogue on tanh(g_h @ B + bias) (A = g_h,  LDA=512)
// ---------------------------------------------------------------------------
template <int MODE, int LDA, int LDB>
__global__ __launch_bounds__(128, 2)
void gemm_spline(const float* __restrict__ Ag, const float* __restrict__ Bg,
                 const float* __restrict__ bias, const float* __restrict__ v_in,
                 float* __restrict__ outp) {
    __shared__ __align__(16) float smem[SMEM_FLOATS];
    __shared__ float partial2[128];

    const int t = threadIdx.x;
    const int wid = t >> 5, lane = t & 31;
    const int warp_m = wid >> 1, warp_n = wid & 1;
    const int gr = lane >> 2, tc = lane & 3;
    const int m0 = blockIdx.y * 128, n0 = blockIdx.x * 128;

    const float* Aptr = (MODE == 0) ? Ag : g_h;
    const uint32_t sbase = (uint32_t)__cvta_generic_to_shared(smem);

    float acc[4][8][4];
#pragma unroll
    for (int mt = 0; mt < 4; mt++)
#pragma unroll
        for (int nt = 0; nt < 8; nt++)
#pragma unroll
            for (int r = 0; r < 4; r++) acc[mt][nt][r] = 0.f;

    const int b_nq = t & 31, b_k = t >> 5;

    auto prefetch = [&](int it, int buf) {
        const int k0 = it * 16;
        const float* asrc = Aptr + (size_t)(m0 + t) * LDA + k0;
        uint32_t adst = sbase + (uint32_t)(buf * A_BUF + t * A_STRIDE) * 4u;
#pragma unroll
        for (int q = 0; q < 4; q++) CPA16(adst + q * 16, asrc + q * 4);
        const float* bsrc = Bg + (size_t)(k0 + b_k) * LDB + n0 + b_nq * 4;
        uint32_t bdst = sbase + (uint32_t)(B_OFF + buf * B_BUF + b_k * B_STRIDE + b_nq * 4) * 4u;
#pragma unroll
        for (int q = 0; q < 4; q++)
            CPA16(bdst + (uint32_t)(q * 4 * B_STRIDE) * 4u, bsrc + (size_t)q * 4 * LDB);
        asm volatile("cp.async.commit_group;\n");
    };

    prefetch(0, 0);

    for (int it = 0; it < 32; ++it) {
        if (it < 31) prefetch(it + 1, (it + 1) & 1);
        else asm volatile("cp.async.commit_group;\n");
        asm volatile("cp.async.wait_group 1;\n");
        __syncthreads();

        const float* As = smem + (it & 1) * A_BUF;
        const float* Bs = smem + B_OFF + (it & 1) * B_BUF;
#pragma unroll
        for (int ks = 0; ks < 2; ks++) {
            uint32_t af[4][4];
            uint32_t bf[8][2];
#pragma unroll
            for (int mt = 0; mt < 4; mt++) {
                const int R = warp_m * 64 + mt * 16 + gr;
                float a0 = As[R * A_STRIDE + ks * 8 + tc];
                float a1 = As[(R + 8) * A_STRIDE + ks * 8 + tc];
                float a2 = As[R * A_STRIDE + ks * 8 + tc + 4];
                float a3 = As[(R + 8) * A_STRIDE + ks * 8 + tc + 4];
                if (MODE == 0) { a0 -= 0.5f; a1 -= 0.5f; a2 -= 0.5f; a3 -= 0.5f; }
                af[mt][0] = f2tf32(a0); af[mt][1] = f2tf32(a1);
                af[mt][2] = f2tf32(a2); af[mt][3] = f2tf32(a3);
            }
#pragma unroll
            for (int nt = 0; nt < 8; nt++) {
                const int C = warp_n * 64 + nt * 8 + gr;
                bf[nt][0] = f2tf32(Bs[(ks * 8 + tc) * B_STRIDE + C]);
                bf[nt][1] = f2tf32(Bs[(ks * 8 + tc + 4) * B_STRIDE + C]);
            }
#pragma unroll
            for (int mt = 0; mt < 4; mt++)
#pragma unroll
                for (int nt = 0; nt < 8; nt++)
                    mma_tf32(acc[mt][nt], af[mt], bf[nt]);
        }
        __syncthreads();
    }

    if (MODE == 0) {
        // tanh(acc + bias) -> g_h, direct fragment stores (st.64, full sectors)
#pragma unroll
        for (int mt = 0; mt < 4; mt++) {
            const int R = m0 + warp_m * 64 + mt * 16 + gr;
#pragma unroll
            for (int nt = 0; nt < 8; nt++) {
                const int C = n0 + warp_n * 64 + nt * 8 + tc * 2;
                const float b0 = bias[C], b1 = bias[C + 1];
                float2 v0 = {fast_tanh(acc[mt][nt][0] + b0), fast_tanh(acc[mt][nt][1] + b1)};
                float2 v1 = {fast_tanh(acc[mt][nt][2] + b0), fast_tanh(acc[mt][nt][3] + b1)};
                *(float2*)&g_h[(size_t)R * HDIM + C] = v0;
                *(float2*)&g_h[(size_t)(R + 8) * HDIM + C] = v1;
            }
        }
        return;
    }

    // ---- MODE 1: spline epilogue, two 64-row phases staged through smem ----
    float* U = smem;  // 64 x 132 (reuses pipeline buffers)
    const int row = t & 63;
    const int gq = (t >> 6) * 4;  // 4 of the 8 h-groups in this 128-col tile

#pragma unroll
    for (int p = 0; p < 2; p++) {
        __syncthreads();
        if (warp_m == p) {
#pragma unroll
            for (int mt = 0; mt < 4; mt++) {
                const int rl = mt * 16 + gr;
#pragma unroll
                for (int nt = 0; nt < 8; nt++) {
                    const int cl = warp_n * 64 + nt * 8 + tc * 2;
                    const float b0 = bias[n0 + cl], b1 = bias[n0 + cl + 1];
                    U[rl * 132 + cl] = fast_tanh(acc[mt][nt][0] + b0);
                    U[rl * 132 + cl + 1] = fast_tanh(acc[mt][nt][1] + b1);
                    U[(rl + 8) * 132 + cl] = fast_tanh(acc[mt][nt][2] + b0);
                    U[(rl + 8) * 132 + cl + 1] = fast_tanh(acc[mt][nt][3] + b1);
                }
            }
        }
        __syncthreads();

        const int grow = m0 + p * 64 + row;
        const int hbase = (n0 >> 4) + gq;
        float4 av = *(const float4*)&v_in[(size_t)grow * 1024 + 512 + hbase];
        float4 ov;
        float nlp = 0.f;
#pragma unroll
        for (int gg = 0; gg < 4; gg++) {
            const float a = (&av.x)[gg];
            const float tk = a * 16.0f;  // exact
            int k = (int)ceilf(tk) - 1;
            k = k < 0 ? 0 : (k > 15 ? 15 : k);
            const float4* up = (const float4*)&U[row * 132 + (gq + gg) * 16];
            float Z = 0.f, prefix = 0.f, sk = 0.f, uk = 0.f;
#pragma unroll
            for (int j4 = 0; j4 < 4; j4++) {
                float4 u4 = up[j4];
#pragma unroll
                for (int jj = 0; jj < 4; jj++) {
                    const int j = j4 * 4 + jj;
                    const float u = (&u4.x)[jj];
                    const float s = exp_poly(u);
                    Z += s;
                    prefix += (j < k) ? s : 0.f;
                    if (j == k) { sk = s; uk = u; }
                }
            }
            const float alpha = tk - (float)k;
            (&ov.x)[gg] = __fdividef(fmaf(alpha, sk, prefix), Z);
            nlp += __logf(Z) - uk;  // = -log p_k
        }
        *(float4*)&outp[(size_t)grow * 1024 + 512 + hbase] = ov;
        partial2[t] = nlp;
        __syncthreads();
        if (t < 64)
            g_partial[(size_t)(m0 + p * 64 + t) * NTILES_N + blockIdx.x] =
                partial2[t] + partial2[t + 64];
    }
}

// ---------------------------------------------------------------------------
__global__ void k_copy_passive(const float* __restrict__ v_in, float* __restrict__ out) {
    int i = blockIdx.x * 256 + threadIdx.x;
    int r = i >> 7;
    int c = i & 127;
    const float4* vi = (const float4*)v_in;
    float4* o = (float4*)out;
    o[r * 256 + c] = vi[r * 256 + c];
}

__global__ void k_reduce(const float* __restrict__ log_density,
                         float* __restrict__ out, int ld_offset) {
    int r = blockIdx.x * 256 + threadIdx.x;
    if (r >= BATCH) return;
    float s = log_density[r];
    const float4* p4 = (const float4*)&g_partial[(size_t)r * NTILES_N];
#pragma unroll
    for (int i = 0; i < NTILES_N / 4; i++) {
        float4 v = p4[i];
        s += v.x + v.y + v.z + v.w;
    }
    out[ld_offset + r] = s;
}

// ---------------------------------------------------------------------------
extern "C" void kernel_launch(void* const* d_in, const int* in_sizes, int n_in,
                              void* d_out, int out_size) {
    const float* v_in        = (const float*)d_in[0];
    const float* log_density = (const float*)d_in[1];
    const float* W1          = (const float*)d_in[2];
    const float* b1          = (const float*)d_in[3];
    const float* W2          = (const float*)d_in[4];
    const float* b2          = (const float*)d_in[5];
    float* out = (float*)d_out;

    int ld_offset = out_size - BATCH;

    k_copy_passive<<<BATCH * 128 / 256, 256>>>(v_in, out);
    gemm_spline<0, 1024, 512><<<dim3(HDIM / 128, BATCH / 128), 128>>>(
        v_in, W1, b1, v_in, out);
    gemm_spline<1, 512, 8192><<<dim3(NBIG / 128, BATCH / 128), 128>>>(
        nullptr, W2, b2, v_in, out);
    k_reduce<<<BATCH / 256, 256>>>(log_density, out, ld_offset);
}

// round 12
// speedup vs baseline: 5.6263x; 1.5163x over previous
#include <cuda_runtime.h>
#include <cuda_fp16.h>
#include <cstdint>

constexpr int BATCH = 8192;
constexpr int HDIM  = 512;
constexpr int NBIG  = 8192;       // H*K columns of GEMM2
constexpr int NTILES_N = 64;      // NBIG / 128

// fp16 operands (device globals: no allocation allowed).
// NOTE: never passed as kernel arguments from host — device-side selection only.
__device__ __half g_A1[BATCH * HDIM];     // (v_passive - 0.5)
__device__ __half g_W1T[HDIM * HDIM];     // W1 transposed: [n][k]
__device__ __half g_W2T[NBIG * HDIM];     // W2 transposed: [n][k]
__device__ __half g_h[BATCH * HDIM];      // tanh(layer1) as fp16
__device__ float  g_partial[BATCH * NTILES_N];

__device__ __forceinline__ float fast_tanh(float x) {
    float y; asm("tanh.approx.f32 %0, %1;" : "=f"(y) : "f"(x)); return y;
}
// e^u for u in [-1,1], degree-8 Taylor (rel err ~7e-6), pure FMA pipe
__device__ __forceinline__ float exp_poly(float u) {
    float r = 2.48015873e-05f;
    r = fmaf(r, u, 1.98412698e-04f); r = fmaf(r, u, 1.38888889e-03f);
    r = fmaf(r, u, 8.33333333e-03f); r = fmaf(r, u, 4.16666667e-02f);
    r = fmaf(r, u, 1.66666667e-01f); r = fmaf(r, u, 0.5f);
    r = fmaf(r, u, 1.0f); r = fmaf(r, u, 1.0f);
    return r;
}

__device__ __forceinline__ void mma_fp16(float* c, const uint32_t* a, const uint32_t* b) {
    asm volatile(
        "mma.sync.aligned.m16n8k16.row.col.f32.f16.f16.f32 "
        "{%0,%1,%2,%3}, {%4,%5,%6,%7}, {%8,%9}, {%0,%1,%2,%3};\n"
        : "+f"(c[0]), "+f"(c[1]), "+f"(c[2]), "+f"(c[3])
        : "r"(a[0]), "r"(a[1]), "r"(a[2]), "r"(a[3]), "r"(b[0]), "r"(b[1]));
}

#define CPA16(dst, src) \
    asm volatile("cp.async.cg.shared.global [%0], [%1], 16;\n" :: "r"(dst), "l"(src))

// smem (halves): A[2][128][40], B[2][128][40]. 32 payload halves + 8 pad.
// Row stride 40 halves = 20 words -> fragment loads (8 rows x 4 cols of 4B)
// touch all 32 banks: (20*gr + tc) mod 32 distinct for gr in 0..7, tc in 0..3.
constexpr int A_STR   = 40;
constexpr int STAGE_H = 128 * A_STR;        // 5120 halves per stage per operand
constexpr int OFF_B_H = 2 * STAGE_H;        // B starts after both A stages
constexpr int SMEM_HALVES = 4 * STAGE_H;    // 20480 halves = 40960 B

// ---------------------------------------------------------------------------
// fp16 tensor-core GEMM (128x128 tile, BK=32, 4 warps @ 64x64 each).
// MODE 0: C = tanh(g_A1 @ g_W1T^T + b1) -> g_h (fp16)
// MODE 1: fused spline epilogue on tanh(g_h @ g_W2T^T + b2) -> out + g_partial
// ---------------------------------------------------------------------------
template <int MODE>
__global__ __launch_bounds__(128, 2)
void gemm_fp16(const float* __restrict__ bias, const float* __restrict__ v_in,
               float* __restrict__ outp) {
    __shared__ __align__(16) __half sm[SMEM_HALVES];
    __shared__ float partial2[128];

    // Device-side pointer selection (host-passed __device__ symbols read host
    // memory via ATS on GB300 -- the round-11 bug).
    const __half* __restrict__ Ag = (MODE == 0) ? g_A1 : g_h;
    const __half* __restrict__ Bg = (MODE == 0) ? g_W1T : g_W2T;

    const int t = threadIdx.x;
    const int wid = t >> 5, lane = t & 31;
    const int warp_m = wid >> 1, warp_n = wid & 1;
    const int gr = lane >> 2, tc = lane & 3;
    const int m0 = blockIdx.y * 128, n0 = blockIdx.x * 128;

    const uint32_t sbase = (uint32_t)__cvta_generic_to_shared(sm);

    float acc[4][8][4];
#pragma unroll
    for (int mt = 0; mt < 4; mt++)
#pragma unroll
        for (int nt = 0; nt < 8; nt++)
#pragma unroll
            for (int r = 0; r < 4; r++) acc[mt][nt][r] = 0.f;

    auto prefetch = [&](int it, int buf) {
        const int k0 = it * 32;
        const __half* asrc = Ag + (size_t)(m0 + t) * HDIM + k0;
        const __half* bsrc = Bg + (size_t)(n0 + t) * HDIM + k0;
        const uint32_t adst = sbase + (uint32_t)(buf * STAGE_H + t * A_STR) * 2u;
        const uint32_t bdst = sbase + (uint32_t)(OFF_B_H + buf * STAGE_H + t * A_STR) * 2u;
#pragma unroll
        for (int q = 0; q < 4; q++) {
            CPA16(adst + q * 16, asrc + q * 8);
            CPA16(bdst + q * 16, bsrc + q * 8);
        }
        asm volatile("cp.async.commit_group;\n");
    };

    prefetch(0, 0);

    for (int it = 0; it < 16; ++it) {
        if (it < 15) prefetch(it + 1, (it + 1) & 1);
        else asm volatile("cp.async.commit_group;\n");
        asm volatile("cp.async.wait_group 1;\n");
        __syncthreads();

        const __half* As = sm + (it & 1) * STAGE_H;
        const __half* Bs = sm + OFF_B_H + (it & 1) * STAGE_H;
#pragma unroll
        for (int ks = 0; ks < 2; ks++) {
            const int ko = ks * 16 + 2 * tc;
            uint32_t af[4][4], bf[8][2];
#pragma unroll
            for (int mt = 0; mt < 4; mt++) {
                const int R = warp_m * 64 + mt * 16 + gr;
                af[mt][0] = *(const uint32_t*)(As + R * A_STR + ko);
                af[mt][1] = *(const uint32_t*)(As + (R + 8) * A_STR + ko);
                af[mt][2] = *(const uint32_t*)(As + R * A_STR + ko + 8);
                af[mt][3] = *(const uint32_t*)(As + (R + 8) * A_STR + ko + 8);
            }
#pragma unroll
            for (int nt = 0; nt < 8; nt++) {
                const int Rn = warp_n * 64 + nt * 8 + gr;
                bf[nt][0] = *(const uint32_t*)(Bs + Rn * A_STR + ko);
                bf[nt][1] = *(const uint32_t*)(Bs + Rn * A_STR + ko + 8);
            }
#pragma unroll
            for (int mt = 0; mt < 4; mt++)
#pragma unroll
                for (int nt = 0; nt < 8; nt++)
                    mma_fp16(acc[mt][nt], af[mt], bf[nt]);
        }
        __syncthreads();
    }

    if (MODE == 0) {
        // tanh(acc + bias) -> g_h as fp16 (half2 stores)
#pragma unroll
        for (int mt = 0; mt < 4; mt++) {
            const int R = m0 + warp_m * 64 + mt * 16 + gr;
#pragma unroll
            for (int nt = 0; nt < 8; nt++) {
                const int C = n0 + warp_n * 64 + nt * 8 + tc * 2;
                const float b0 = bias[C], b1 = bias[C + 1];
                __half2 v0 = __floats2half2_rn(fast_tanh(acc[mt][nt][0] + b0),
                                               fast_tanh(acc[mt][nt][1] + b1));
                __half2 v1 = __floats2half2_rn(fast_tanh(acc[mt][nt][2] + b0),
                                               fast_tanh(acc[mt][nt][3] + b1));
                *(__half2*)&g_h[(size_t)R * HDIM + C] = v0;
                *(__half2*)&g_h[(size_t)(R + 8) * HDIM + C] = v1;
            }
        }
        return;
    }

    // ---- MODE 1: spline epilogue, two 64-row phases staged through smem ----
    float* U = (float*)sm;  // 64 x 132 floats (33.8 KB, overlays pipeline bufs)
    const int row = t & 63;
    const int gq = (t >> 6) * 4;

#pragma unroll
    for (int p = 0; p < 2; p++) {
        __syncthreads();
        if (warp_m == p) {
#pragma unroll
            for (int mt = 0; mt < 4; mt++) {
                const int rl = mt * 16 + gr;
#pragma unroll
                for (int nt = 0; nt < 8; nt++) {
                    const int cl = warp_n * 64 + nt * 8 + tc * 2;
                    const float b0 = bias[n0 + cl], b1 = bias[n0 + cl + 1];
                    U[rl * 132 + cl] = fast_tanh(acc[mt][nt][0] + b0);
                    U[rl * 132 + cl + 1] = fast_tanh(acc[mt][nt][1] + b1);
                    U[(rl + 8) * 132 + cl] = fast_tanh(acc[mt][nt][2] + b0);
                    U[(rl + 8) * 132 + cl + 1] = fast_tanh(acc[mt][nt][3] + b1);
                }
            }
        }
        __syncthreads();

        const int grow = m0 + p * 64 + row;
        const int hbase = (n0 >> 4) + gq;
        float4 av = *(const float4*)&v_in[(size_t)grow * 1024 + 512 + hbase];
        float4 ov;
        float nlp = 0.f;
#pragma unroll
        for (int gg = 0; gg < 4; gg++) {
            const float a = (&av.x)[gg];
            const float tk = a * 16.0f;  // exact
            int k = (int)ceilf(tk) - 1;
            k = k < 0 ? 0 : (k > 15 ? 15 : k);
            const float4* up = (const float4*)&U[row * 132 + (gq + gg) * 16];
            float Z = 0.f, prefix = 0.f, sk = 0.f, uk = 0.f;
#pragma unroll
            for (int j4 = 0; j4 < 4; j4++) {
                float4 u4 = up[j4];
#pragma unroll
                for (int jj = 0; jj < 4; jj++) {
                    const int j = j4 * 4 + jj;
                    const float u = (&u4.x)[jj];
                    const float s = exp_poly(u);
                    Z += s;
                    prefix += (j < k) ? s : 0.f;
                    if (j == k) { sk = s; uk = u; }
                }
            }
            const float alpha = tk - (float)k;
            (&ov.x)[gg] = __fdividef(fmaf(alpha, sk, prefix), Z);
            nlp += __logf(Z) - uk;  // = -log p_k
        }
        *(float4*)&outp[(size_t)grow * 1024 + 512 + hbase] = ov;
        partial2[t] = nlp;
        __syncthreads();
        if (t < 64)
            g_partial[(size_t)(m0 + p * 64 + t) * NTILES_N + blockIdx.x] =
                partial2[t] + partial2[t + 64];
    }
}

// ---------------------------------------------------------------------------
// Prep kernels (destinations selected device-side)
// ---------------------------------------------------------------------------
__global__ void k_prep_A(const float* __restrict__ v_in) {
    int i = blockIdx.x * 256 + threadIdx.x;  // over BATCH*128 float4
    int r = i >> 7, c4 = i & 127;
    float4 v = ((const float4*)v_in)[(size_t)r * 256 + c4];
    __half2 h0 = __floats2half2_rn(v.x - 0.5f, v.y - 0.5f);
    __half2 h1 = __floats2half2_rn(v.z - 0.5f, v.w - 0.5f);
    uint2 pk = make_uint2(*(uint32_t*)&h0, *(uint32_t*)&h1);
    ((uint2*)g_A1)[(size_t)r * 128 + c4] = pk;
}

// Tiled transpose to fp16: dst[n][k] = in[k][n]. WHICH selects destination.
template <int WHICH, int NCOLS>
__global__ void k_prep_WT(const float* __restrict__ in) {
    __half* __restrict__ outT = (WHICH == 0) ? g_W1T : g_W2T;
    __shared__ float tile[32][33];
    const int tx = threadIdx.x, ty = threadIdx.y;  // 32 x 8
    const int n0 = blockIdx.x * 32, k0 = blockIdx.y * 32;
#pragma unroll
    for (int i = 0; i < 4; i++)
        tile[ty + i * 8][tx] = in[(size_t)(k0 + ty + i * 8) * NCOLS + n0 + tx];
    __syncthreads();
#pragma unroll
    for (int i = 0; i < 4; i++)
        outT[(size_t)(n0 + ty + i * 8) * HDIM + k0 + tx] =
            __float2half_rn(tile[tx][ty + i * 8]);
}

__global__ void k_copy_passive(const float* __restrict__ v_in, float* __restrict__ out) {
    int i = blockIdx.x * 256 + threadIdx.x;
    int r = i >> 7, c = i & 127;
    ((float4*)out)[(size_t)r * 256 + c] = ((const float4*)v_in)[(size_t)r * 256 + c];
}

__global__ void k_reduce(const float* __restrict__ log_density,
                         float* __restrict__ out, int ld_offset) {
    int r = blockIdx.x * 256 + threadIdx.x;
    if (r >= BATCH) return;
    float s = log_density[r];
    const float4* p4 = (const float4*)&g_partial[(size_t)r * NTILES_N];
#pragma unroll
    for (int i = 0; i < NTILES_N / 4; i++) {
        float4 v = p4[i];
        s += v.x + v.y + v.z + v.w;
    }
    out[ld_offset + r] = s;
}

// ---------------------------------------------------------------------------
extern "C" void kernel_launch(void* const* d_in, const int* in_sizes, int n_in,
                              void* d_out, int out_size) {
    const float* v_in        = (const float*)d_in[0];
    const float* log_density = (const float*)d_in[1];
    const float* W1          = (const float*)d_in[2];
    const float* b1          = (const float*)d_in[3];
    const float* W2          = (const float*)d_in[4];
    const float* b2          = (const float*)d_in[5];
    float* out = (float*)d_out;
    const int ld_offset = out_size - BATCH;

    k_copy_passive<<<BATCH * 128 / 256, 256>>>(v_in, out);
    k_prep_A<<<BATCH * 128 / 256, 256>>>(v_in);
    k_prep_WT<0, HDIM><<<dim3(HDIM / 32, HDIM / 32), dim3(32, 8)>>>(W1);
    k_prep_WT<1, NBIG><<<dim3(NBIG / 32, HDIM / 32), dim3(32, 8)>>>(W2);
    gemm_fp16<0><<<dim3(HDIM / 128, BATCH / 128), 128>>>(b1, v_in, out);
    gemm_fp16<1><<<dim3(NBIG / 128, BATCH / 128), 128>>>(b2, v_in, out);
    k_reduce<<<BATCH / 256, 256>>>(log_density, out, ld_offset);
}

// round 13
// speedup vs baseline: 7.1097x; 1.2637x over previous
#include <cuda_runtime.h>
#include <cuda_fp16.h>
#include <cstdint>

constexpr int BATCH = 8192;
constexpr int HDIM  = 512;
constexpr int NBIG  = 8192;       // H*K columns of GEMM2
constexpr int NTILES_N = 64;      // NBIG / 128

// fp16 operands (device globals; selected device-side only — GB300 ATS trap)
__device__ __half g_A1[BATCH * HDIM];     // (v_passive - 0.5)
__device__ __half g_W1T[HDIM * HDIM];     // W1 transposed: [n][k]
__device__ __half g_W2T[NBIG * HDIM];     // W2 transposed: [n][k]
__device__ __half g_h[BATCH * HDIM];      // tanh(layer1) as fp16
__device__ float  g_partial[BATCH * NTILES_N];

__device__ __forceinline__ float fast_tanh(float x) {
    float y; asm("tanh.approx.f32 %0, %1;" : "=f"(y) : "f"(x)); return y;
}
// e^u for u in [-1,1], degree-8 Taylor (rel err ~7e-6), pure FMA pipe
__device__ __forceinline__ float exp_poly(float u) {
    float r = 2.48015873e-05f;
    r = fmaf(r, u, 1.98412698e-04f); r = fmaf(r, u, 1.38888889e-03f);
    r = fmaf(r, u, 8.33333333e-03f); r = fmaf(r, u, 4.16666667e-02f);
    r = fmaf(r, u, 1.66666667e-01f); r = fmaf(r, u, 0.5f);
    r = fmaf(r, u, 1.0f); r = fmaf(r, u, 1.0f);
    return r;
}

__device__ __forceinline__ void mma_fp16(float* c, const uint32_t* a, const uint32_t* b) {
    asm volatile(
        "mma.sync.aligned.m16n8k16.row.col.f32.f16.f16.f32 "
        "{%0,%1,%2,%3}, {%4,%5,%6,%7}, {%8,%9}, {%0,%1,%2,%3};\n"
        : "+f"(c[0]), "+f"(c[1]), "+f"(c[2]), "+f"(c[3])
        : "r"(a[0]), "r"(a[1]), "r"(a[2]), "r"(a[3]), "r"(b[0]), "r"(b[1]));
}
__device__ __forceinline__ void ldsm_x4(uint32_t* r, uint32_t addr) {
    asm volatile("ldmatrix.sync.aligned.m8n8.x4.shared.b16 {%0,%1,%2,%3}, [%4];"
                 : "=r"(r[0]), "=r"(r[1]), "=r"(r[2]), "=r"(r[3]) : "r"(addr));
}

#define CPA16(dst, src) \
    asm volatile("cp.async.cg.shared.global [%0], [%1], 16;\n" :: "r"(dst), "l"(src))

// smem (halves): A[2][128][40], B[2][128][40]. 32 payload halves + 8 pad.
// Row stride 40 halves = 20 words; 8 consecutive rows start at words
// {0,20,8,28,16,4,24,12} mod 32 -> each ldmatrix 8-lane phase tiles all banks.
constexpr int A_STR   = 40;
constexpr int STAGE_H = 128 * A_STR;        // 5120 halves per stage per operand
constexpr int OFF_B_H = 2 * STAGE_H;
constexpr int SMEM_HALVES = 4 * STAGE_H;    // 40960 B

// ---------------------------------------------------------------------------
// fp16 tensor-core GEMM (128x128 tile, BK=32, 256 thr, 8 warps @ 32x64 each).
// MODE 0: C = tanh(g_A1 @ g_W1T^T + b1) -> g_h (fp16)
// MODE 1: fused spline epilogue on tanh(g_h @ g_W2T^T + b2) -> out + g_partial
// ---------------------------------------------------------------------------
template <int MODE>
__global__ __launch_bounds__(256, 2)
void gemm_fp16(const float* __restrict__ bias, const float* __restrict__ v_in,
               float* __restrict__ outp) {
    __shared__ __align__(16) __half sm[SMEM_HALVES];
    __shared__ float partial2[256];

    const __half* __restrict__ Ag = (MODE == 0) ? g_A1 : g_h;
    const __half* __restrict__ Bg = (MODE == 0) ? g_W1T : g_W2T;

    const int t = threadIdx.x;
    const int wid = t >> 5, lane = t & 31;
    const int warp_m = wid >> 1, warp_n = wid & 1;   // 4 x 2
    const int gr = lane >> 2, tc = lane & 3;
    const int m0 = blockIdx.y * 128, n0 = blockIdx.x * 128;

    const uint32_t sbase = (uint32_t)__cvta_generic_to_shared(sm);

    // per-lane ldmatrix source offsets (halves), within a stage
    // A (x4): m = warp_m*32 + mt*16 + (l%8) + ((l/8)&1)*8 ; k = ks*16 + (l/16)*8
    const uint32_t a_lm = (uint32_t)((warp_m * 32 + (lane & 7) + ((lane >> 3) & 1) * 8) * A_STR
                                     + (lane >> 4) * 8);
    // B (x4): n = warp_n*64 + ntp*16 + (l%8) + (l/16)*8 ; k = ks*16 + ((l/8)&1)*8
    const uint32_t b_lm = (uint32_t)(OFF_B_H
                                     + (warp_n * 64 + (lane & 7) + (lane >> 4) * 8) * A_STR
                                     + ((lane >> 3) & 1) * 8);

    float acc[2][8][4];
#pragma unroll
    for (int mt = 0; mt < 2; mt++)
#pragma unroll
        for (int nt = 0; nt < 8; nt++)
#pragma unroll
            for (int r = 0; r < 4; r++) acc[mt][nt][r] = 0.f;

    auto prefetch = [&](int it, int buf) {
        const int k0 = it * 32;
        const int row = t >> 1, kq = (t & 1) * 16;
        const __half* asrc = Ag + (size_t)(m0 + row) * HDIM + k0 + kq;
        const __half* bsrc = Bg + (size_t)(n0 + row) * HDIM + k0 + kq;
        const uint32_t adst = sbase + (uint32_t)(buf * STAGE_H + row * A_STR + kq) * 2u;
        const uint32_t bdst = sbase + (uint32_t)(OFF_B_H + buf * STAGE_H + row * A_STR + kq) * 2u;
        CPA16(adst, asrc);
        CPA16(adst + 16, asrc + 8);
        CPA16(bdst, bsrc);
        CPA16(bdst + 16, bsrc + 8);
        asm volatile("cp.async.commit_group;\n");
    };

    prefetch(0, 0);

    for (int it = 0; it < 16; ++it) {
        if (it < 15) prefetch(it + 1, (it + 1) & 1);
        else asm volatile("cp.async.commit_group;\n");
        asm volatile("cp.async.wait_group 1;\n");
        __syncthreads();

        const uint32_t stg = sbase + (uint32_t)((it & 1) * STAGE_H) * 2u;
#pragma unroll
        for (int ks = 0; ks < 2; ks++) {
            uint32_t af[2][4], bf[8][2];
#pragma unroll
            for (int mt = 0; mt < 2; mt++)
                ldsm_x4(af[mt], stg + (a_lm + mt * 16 * A_STR + ks * 16) * 2u);
#pragma unroll
            for (int ntp = 0; ntp < 4; ntp++) {
                uint32_t br[4];
                ldsm_x4(br, stg + (b_lm + ntp * 16 * A_STR + ks * 16) * 2u);
                bf[2 * ntp][0] = br[0]; bf[2 * ntp][1] = br[1];
                bf[2 * ntp + 1][0] = br[2]; bf[2 * ntp + 1][1] = br[3];
            }
#pragma unroll
            for (int mt = 0; mt < 2; mt++)
#pragma unroll
                for (int nt = 0; nt < 8; nt++)
                    mma_fp16(acc[mt][nt], af[mt], bf[nt]);
        }
        __syncthreads();
    }

    if (MODE == 0) {
        // tanh(acc + bias) -> g_h as fp16 (half2 stores)
#pragma unroll
        for (int mt = 0; mt < 2; mt++) {
            const int R = m0 + warp_m * 32 + mt * 16 + gr;
#pragma unroll
            for (int nt = 0; nt < 8; nt++) {
                const int C = n0 + warp_n * 64 + nt * 8 + tc * 2;
                const float b0 = bias[C], b1 = bias[C + 1];
                __half2 v0 = __floats2half2_rn(fast_tanh(acc[mt][nt][0] + b0),
                                               fast_tanh(acc[mt][nt][1] + b1));
                __half2 v1 = __floats2half2_rn(fast_tanh(acc[mt][nt][2] + b0),
                                               fast_tanh(acc[mt][nt][3] + b1));
                *(__half2*)&g_h[(size_t)R * HDIM + C] = v0;
                *(__half2*)&g_h[(size_t)(R + 8) * HDIM + C] = v1;
            }
        }
        return;
    }

    // ---- MODE 1: spline epilogue, two 64-row phases staged through smem ----
    float* U = (float*)sm;  // 64 x 132 floats = 33.8 KB (overlays pipeline)
    const int row = t & 63;
    const int gq = (t >> 6) * 2;   // 4 thread-groups x 2 h-groups = 8

#pragma unroll
    for (int p = 0; p < 2; p++) {
        __syncthreads();
        if ((warp_m >> 1) == p) {   // warps 2p, 2p+1 own rows [p*64, p*64+64)
#pragma unroll
            for (int mt = 0; mt < 2; mt++) {
                const int rl = (warp_m & 1) * 32 + mt * 16 + gr;
#pragma unroll
                for (int nt = 0; nt < 8; nt++) {
                    const int cl = warp_n * 64 + nt * 8 + tc * 2;
                    const float b0 = bias[n0 + cl], b1 = bias[n0 + cl + 1];
                    U[rl * 132 + cl] = fast_tanh(acc[mt][nt][0] + b0);
                    U[rl * 132 + cl + 1] = fast_tanh(acc[mt][nt][1] + b1);
                    U[(rl + 8) * 132 + cl] = fast_tanh(acc[mt][nt][2] + b0);
                    U[(rl + 8) * 132 + cl + 1] = fast_tanh(acc[mt][nt][3] + b1);
                }
            }
        }
        __syncthreads();

        const int grow = m0 + p * 64 + row;
        const int hbase = (n0 >> 4) + gq;
        float2 av = *(const float2*)&v_in[(size_t)grow * 1024 + 512 + hbase];
        float2 ov;
        float nlp = 0.f;
#pragma unroll
        for (int gg = 0; gg < 2; gg++) {
            const float a = (&av.x)[gg];
            const float tk = a * 16.0f;  // exact
            int k = (int)ceilf(tk) - 1;
            k = k < 0 ? 0 : (k > 15 ? 15 : k);
            const float4* up = (const float4*)&U[row * 132 + (gq + gg) * 16];
            float Z = 0.f, prefix = 0.f, sk = 0.f, uk = 0.f;
#pragma unroll
            for (int j4 = 0; j4 < 4; j4++) {
                float4 u4 = up[j4];
#pragma unroll
                for (int jj = 0; jj < 4; jj++) {
                    const int j = j4 * 4 + jj;
                    const float u = (&u4.x)[jj];
                    const float s = exp_poly(u);
                    Z += s;
                    prefix += (j < k) ? s : 0.f;
                    if (j == k) { sk = s; uk = u; }
                }
            }
            const float alpha = tk - (float)k;
            (&ov.x)[gg] = __fdividef(fmaf(alpha, sk, prefix), Z);
            nlp += __logf(Z) - uk;  // = -log p_k
        }
        *(float2*)&outp[(size_t)grow * 1024 + 512 + hbase] = ov;
        partial2[t] = nlp;
        __syncthreads();
        if (t < 64)
            g_partial[(size_t)(m0 + p * 64 + t) * NTILES_N + blockIdx.x] =
                partial2[t] + partial2[t + 64] + partial2[t + 128] + partial2[t + 192];
    }
}

// ---------------------------------------------------------------------------
// Prep kernels (destinations selected device-side)
// ---------------------------------------------------------------------------
// Fused: copy v_passive -> out[:, :512] AND write (v_passive - 0.5) as fp16
__global__ void k_prep_A(const float* __restrict__ v_in, float* __restrict__ out) {
    int i = blockIdx.x * 256 + threadIdx.x;  // over BATCH*128 float4
    int r = i >> 7, c4 = i & 127;
    float4 v = ((const float4*)v_in)[(size_t)r * 256 + c4];
    ((float4*)out)[(size_t)r * 256 + c4] = v;
    __half2 h0 = __floats2half2_rn(v.x - 0.5f, v.y - 0.5f);
    __half2 h1 = __floats2half2_rn(v.z - 0.5f, v.w - 0.5f);
    uint2 pk = make_uint2(*(uint32_t*)&h0, *(uint32_t*)&h1);
    ((uint2*)g_A1)[(size_t)r * 128 + c4] = pk;
}

// Tiled transpose to fp16: dst[n][k] = in[k][n]. WHICH selects destination.
template <int WHICH, int NCOLS>
__global__ void k_prep_WT(const float* __restrict__ in) {
    __half* __restrict__ outT = (WHICH == 0) ? g_W1T : g_W2T;
    __shared__ float tile[32][33];
    const int tx = threadIdx.x, ty = threadIdx.y;  // 32 x 8
    const int n0 = blockIdx.x * 32, k0 = blockIdx.y * 32;
#pragma unroll
    for (int i = 0; i < 4; i++)
        tile[ty + i * 8][tx] = in[(size_t)(k0 + ty + i * 8) * NCOLS + n0 + tx];
    __syncthreads();
#pragma unroll
    for (int i = 0; i < 4; i++)
        outT[(size_t)(n0 + ty + i * 8) * HDIM + k0 + tx] =
            __float2half_rn(tile[tx][ty + i * 8]);
}

__global__ void k_reduce(const float* __restrict__ log_density,
                         float* __restrict__ out, int ld_offset) {
    int r = blockIdx.x * 256 + threadIdx.x;
    if (r >= BATCH) return;
    float s = log_density[r];
    const float4* p4 = (const float4*)&g_partial[(size_t)r * NTILES_N];
#pragma unroll
    for (int i = 0; i < NTILES_N / 4; i++) {
        float4 v = p4[i];
        s += v.x + v.y + v.z + v.w;
    }
    out[ld_offset + r] = s;
}

// ---------------------------------------------------------------------------
extern "C" void kernel_launch(void* const* d_in, const int* in_sizes, int n_in,
                              void* d_out, int out_size) {
    const float* v_in        = (const float*)d_in[0];
    const float* log_density = (const float*)d_in[1];
    const float* W1          = (const float*)d_in[2];
    const float* b1          = (const float*)d_in[3];
    const float* W2          = (const float*)d_in[4];
    const float* b2          = (const float*)d_in[5];
    float* out = (float*)d_out;
    const int ld_offset = out_size - BATCH;

    k_prep_A<<<BATCH * 128 / 256, 256>>>(v_in, out);
    k_prep_WT<0, HDIM><<<dim3(HDIM / 32, HDIM / 32), dim3(32, 8)>>>(W1);
    k_prep_WT<1, NBIG><<<dim3(NBIG / 32, HDIM / 32), dim3(32, 8)>>>(W2);
    gemm_fp16<0><<<dim3(HDIM / 128, BATCH / 128), 256>>>(b1, v_in, out);
    gemm_fp16<1><<<dim3(NBIG / 128, BATCH / 128), 256>>>(b2, v_in, out);
    k_reduce<<<BATCH / 256, 256>>>(log_density, out, ld_offset);
}